// round 1
// baseline (speedup 1.0000x reference)
#include <cuda_runtime.h>

#define N     2048
#define FIN   512
#define F     64
#define NEG_BIG -9.0e15f

// ---------------- scratch (static device allocations only) ----------------
__device__ float g_h[N * F];                 // 512 KB
__device__ float g_S[(size_t)N * N];         // 16 MB: scores, then exp(scores-max) in place
__device__ float g_rowmax[N];
__device__ float g_rowinv[N];                // 1 / rowsum
__device__ float g_opart[4][N * F];          // 2 MB: j-split partials of P@h

#define FMA4(a, s, v) { (a).x += (s)*(v).x; (a).y += (s)*(v).y; (a).z += (s)*(v).z; (a).w += (s)*(v).w; }

// ---------------- init: rowmax = 0 (all unmasked scores are >= 0) ----------
__global__ void init_rowmax() {
    int i = blockIdx.x * blockDim.x + threadIdx.x;
    if (i < N) g_rowmax[i] = 0.0f;
}

// ---------------- K1: h = x @ W  (N x FIN) @ (FIN x F) ---------------------
__global__ __launch_bounds__(256) void k1_gemm_h(const float* __restrict__ x,
                                                 const float* __restrict__ W) {
    __shared__ float xs[16][FIN];   // 32 KB
    __shared__ float ws[32][F];     // 8 KB
    int tid = threadIdx.x;
    int r0 = blockIdx.x * 16;

    const float4* xg  = (const float4*)(x + (size_t)r0 * FIN);
    float4*       xs4 = (float4*)&xs[0][0];
#pragma unroll
    for (int u = 0; u < 8; u++) xs4[tid + u * 256] = xg[tid + u * 256];

    int tx = tid & 15;   // f4 index (4 output features)
    int ty = tid >> 4;   // row within tile
    float4 acc = {0.f, 0.f, 0.f, 0.f};

    for (int kt = 0; kt < FIN; kt += 32) {
        __syncthreads();
        const float4* wg  = (const float4*)(W + (size_t)kt * F);
        float4*       ws4 = (float4*)&ws[0][0];
        ws4[tid]       = wg[tid];
        ws4[tid + 256] = wg[tid + 256];
        __syncthreads();
#pragma unroll
        for (int k4 = 0; k4 < 8; k4++) {
            float4 xv = *(const float4*)&xs[ty][kt + k4 * 4];
            float4 w0 = ((const float4*)&ws[k4 * 4 + 0][0])[tx];
            float4 w1 = ((const float4*)&ws[k4 * 4 + 1][0])[tx];
            float4 w2 = ((const float4*)&ws[k4 * 4 + 2][0])[tx];
            float4 w3 = ((const float4*)&ws[k4 * 4 + 3][0])[tx];
            FMA4(acc, xv.x, w0); FMA4(acc, xv.y, w1);
            FMA4(acc, xv.z, w2); FMA4(acc, xv.w, w3);
        }
    }
    *(float4*)&g_h[(size_t)(r0 + ty) * F + tx * 4] = acc;
}

// ---------------- K2: scores S[i,j] = adj ? relu(sum_f |h_i-h_j|*a_f) : NEG_BIG
// 64x64 tile per block, 4i x 4j x 4f register micro-tiles.
// Per-thread f-chunk rotation ((fc+tx)&15) spreads smem banks without swizzle.
__global__ __launch_bounds__(256) void k2_scores(const int* __restrict__ adj,
                                                 const float* __restrict__ a) {
    __shared__ float his[64][F];   // 16 KB  [i][f]
    __shared__ float hjs[64][F];   // 16 KB  [j][f]
    __shared__ float as_[F];

    int tid = threadIdx.x;
    int jb = blockIdx.x, ib = blockIdx.y;

    const float4* hgi = (const float4*)(g_h + (size_t)ib * 64 * F);
    const float4* hgj = (const float4*)(g_h + (size_t)jb * 64 * F);
    float4* hip = (float4*)&his[0][0];
    float4* hjp = (float4*)&hjs[0][0];
#pragma unroll
    for (int u = 0; u < 4; u++) {
        hip[tid + u * 256] = hgi[tid + u * 256];
        hjp[tid + u * 256] = hgj[tid + u * 256];
    }
    if (tid < 16) ((float4*)as_)[tid] = ((const float4*)a)[tid];
    __syncthreads();

    int tx = tid & 15, ty = tid >> 4;
    int i0 = ty * 4, j0 = tx * 4;
    float acc[4][4] = {};

#pragma unroll
    for (int fc = 0; fc < 16; fc++) {
        int c2 = (fc + tx) & 15;               // rotated f-chunk
        float4 av  = ((const float4*)as_)[c2];
        float4 hi0 = *(const float4*)&his[i0 + 0][c2 * 4];
        float4 hi1 = *(const float4*)&his[i0 + 1][c2 * 4];
        float4 hi2 = *(const float4*)&his[i0 + 2][c2 * 4];
        float4 hi3 = *(const float4*)&his[i0 + 3][c2 * 4];
        float4 hj0 = *(const float4*)&hjs[j0 + 0][c2 * 4];
        float4 hj1 = *(const float4*)&hjs[j0 + 1][c2 * 4];
        float4 hj2 = *(const float4*)&hjs[j0 + 2][c2 * 4];
        float4 hj3 = *(const float4*)&hjs[j0 + 3][c2 * 4];
#define ACC1(k, jj) \
        acc[k][jj] += fabsf(hi##k.x - hj##jj.x) * av.x  \
                    + fabsf(hi##k.y - hj##jj.y) * av.y  \
                    + fabsf(hi##k.z - hj##jj.z) * av.z  \
                    + fabsf(hi##k.w - hj##jj.w) * av.w;
        ACC1(0,0) ACC1(0,1) ACC1(0,2) ACC1(0,3)
        ACC1(1,0) ACC1(1,1) ACC1(1,2) ACC1(1,3)
        ACC1(2,0) ACC1(2,1) ACC1(2,2) ACC1(2,3)
        ACC1(3,0) ACC1(3,1) ACC1(3,2) ACC1(3,3)
#undef ACC1
    }

    int gi0 = ib * 64 + i0, gj0 = jb * 64 + j0;
#pragma unroll
    for (int k = 0; k < 4; k++) {
        int4 ad = *(const int4*)&adj[(size_t)(gi0 + k) * N + gj0];
        float4 s;
        s.x = (ad.x > 0) ? fmaxf(acc[k][0], 0.f) : NEG_BIG;
        s.y = (ad.y > 0) ? fmaxf(acc[k][1], 0.f) : NEG_BIG;
        s.z = (ad.z > 0) ? fmaxf(acc[k][2], 0.f) : NEG_BIG;
        s.w = (ad.w > 0) ? fmaxf(acc[k][3], 0.f) : NEG_BIG;
        float m = fmaxf(fmaxf(s.x, s.y), fmaxf(s.z, s.w));
#pragma unroll
        for (int o = 8; o >= 1; o >>= 1)
            m = fmaxf(m, __shfl_xor_sync(0xffffffffu, m, o));
        if (tx == 0 && m >= 0.f)
            atomicMax((int*)&g_rowmax[gi0 + k], __float_as_int(m)); // valid: values >= 0
        *(float4*)&g_S[(size_t)(gi0 + k) * N + gj0] = s;
    }
}

// ---------------- K2b: in-place P = exp(S - rowmax); rowinv = 1/rowsum -----
__global__ __launch_bounds__(256) void k2b_exp() {
    int i = blockIdx.x;
    int tid = threadIdx.x;
    float m = g_rowmax[i];
    float4* row = (float4*)&g_S[(size_t)i * N];
    float lsum = 0.f;
#pragma unroll
    for (int u = 0; u < 2; u++) {
        float4 v = row[tid + u * 256];
        v.x = __expf(v.x - m);  v.y = __expf(v.y - m);
        v.z = __expf(v.z - m);  v.w = __expf(v.w - m);
        lsum += v.x + v.y + v.z + v.w;
        row[tid + u * 256] = v;
    }
    int lane = tid & 31, w = tid >> 5;
#pragma unroll
    for (int o = 16; o >= 1; o >>= 1) lsum += __shfl_xor_sync(0xffffffffu, lsum, o);
    __shared__ float wsum[8];
    if (lane == 0) wsum[w] = lsum;
    __syncthreads();
    if (tid == 0) {
        float t = 0.f;
#pragma unroll
        for (int q = 0; q < 8; q++) t += wsum[q];
        g_rowinv[i] = 1.0f / t;
    }
}

// ---------------- K3: opart[gy] = P[:, gy-chunk] @ h ----------------------
// 32 i-rows per block x full F; j split into 4 chunks of 512 for parallelism.
__global__ __launch_bounds__(256) void k3_av() {
    __shared__ float Ps[32][128];  // 16 KB
    __shared__ float hs[128][F];   // 32 KB
    int tid = threadIdx.x;
    int ib = blockIdx.x;           // 64 blocks of 32 rows
    int gy = blockIdx.y;           // 4 j-splits
    int tx = tid & 15, ty = tid >> 4;
    float4 acc0 = {0.f,0.f,0.f,0.f}, acc1 = {0.f,0.f,0.f,0.f};

    for (int jt = 0; jt < 4; jt++) {
        int j0 = gy * 512 + jt * 128;
        __syncthreads();
        float4* Ps4 = (float4*)&Ps[0][0];
#pragma unroll
        for (int u = 0; u < 4; u++) {
            int v = tid + u * 256;
            int r = v >> 5, c = v & 31;
            Ps4[v] = *(const float4*)&g_S[(size_t)(ib * 32 + r) * N + j0 + c * 4];
        }
        const float4* hg  = (const float4*)(g_h + (size_t)j0 * F);
        float4*       hs4 = (float4*)&hs[0][0];
#pragma unroll
        for (int u = 0; u < 8; u++) hs4[tid + u * 256] = hg[tid + u * 256];
        __syncthreads();

#pragma unroll 8
        for (int jq = 0; jq < 32; jq++) {
            float4 p0 = *(const float4*)&Ps[ty][jq * 4];
            float4 p1 = *(const float4*)&Ps[ty + 16][jq * 4];
            float4 h0 = ((const float4*)&hs[jq * 4 + 0][0])[tx];
            float4 h1 = ((const float4*)&hs[jq * 4 + 1][0])[tx];
            float4 h2 = ((const float4*)&hs[jq * 4 + 2][0])[tx];
            float4 h3 = ((const float4*)&hs[jq * 4 + 3][0])[tx];
            FMA4(acc0, p0.x, h0); FMA4(acc0, p0.y, h1);
            FMA4(acc0, p0.z, h2); FMA4(acc0, p0.w, h3);
            FMA4(acc1, p1.x, h0); FMA4(acc1, p1.y, h1);
            FMA4(acc1, p1.z, h2); FMA4(acc1, p1.w, h3);
        }
    }
    *(float4*)&g_opart[gy][(size_t)(ib * 32 + ty)      * F + tx * 4] = acc0;
    *(float4*)&g_opart[gy][(size_t)(ib * 32 + ty + 16) * F + tx * 4] = acc1;
}

// ---------------- K4: out = relu((sum of partials) * rowinv) --------------
__global__ __launch_bounds__(256) void k4_final(float* __restrict__ out) {
    int idx = blockIdx.x * blockDim.x + threadIdx.x;   // over N*F/4 float4s
    int i = idx >> 4;                                  // 16 float4 per row
    float inv = g_rowinv[i];
    float4 v0 = ((const float4*)g_opart[0])[idx];
    float4 v1 = ((const float4*)g_opart[1])[idx];
    float4 v2 = ((const float4*)g_opart[2])[idx];
    float4 v3 = ((const float4*)g_opart[3])[idx];
    float4 r;
    r.x = fmaxf((v0.x + v1.x + v2.x + v3.x) * inv, 0.f);
    r.y = fmaxf((v0.y + v1.y + v2.y + v3.y) * inv, 0.f);
    r.z = fmaxf((v0.z + v1.z + v2.z + v3.z) * inv, 0.f);
    r.w = fmaxf((v0.w + v1.w + v2.w + v3.w) * inv, 0.f);
    ((float4*)out)[idx] = r;
}

// ---------------- launch ---------------------------------------------------
extern "C" void kernel_launch(void* const* d_in, const int* in_sizes, int n_in,
                              void* d_out, int out_size) {
    const float* x   = (const float*)d_in[0];
    const int*   adj = (const int*)  d_in[1];
    const float* W   = (const float*)d_in[2];
    const float* a   = (const float*)d_in[3];
    float*       out = (float*)d_out;

    init_rowmax<<<8, 256>>>();
    k1_gemm_h<<<128, 256>>>(x, W);
    dim3 g2(32, 32);
    k2_scores<<<g2, 256>>>(adj, a);
    k2b_exp<<<N, 256>>>();
    dim3 g3(64, 4);
    k3_av<<<g3, 256>>>();
    k4_final<<<128, 256>>>(out);
}